// round 6
// baseline (speedup 1.0000x reference)
#include <cuda_runtime.h>
#include <math.h>

#define BB  4
#define HH  240
#define WW  1216
#define HWc (HH*WW)          // 291840
#define NPX (BB*HWc)         // 1167360

// ping-pong feature buffers (substituted field)
__device__ float g_feat[2][NPX];

// 64B per-pixel record
struct alignas(16) Rec {
    short2 off[8];    // taps 0..3,5..8 offsets, s3.12
    short  affq[8];   // taps 0..3,5..8 affinities, s1.14 (Q=16384)
    float  acen;      // exact fp32 center affinity
    float  fix;       // feat_fix value
};
__device__ Rec g_rec[NPX];

// ---------------- f32x2 helpers (Blackwell packed fp32 pipe) ----------------
__device__ __forceinline__ unsigned long long pk2(float lo, float hi) {
    unsigned long long r;
    asm("mov.b64 %0, {%1,%2};" : "=l"(r) : "f"(lo), "f"(hi));
    return r;
}
__device__ __forceinline__ float2 unpk2(unsigned long long v) {
    float2 f;
    asm("mov.b64 {%0,%1}, %2;" : "=f"(f.x), "=f"(f.y) : "l"(v));
    return f;
}
__device__ __forceinline__ unsigned long long ffma2(unsigned long long a,
                                                    unsigned long long b,
                                                    unsigned long long c) {
    unsigned long long d;
    asm("fma.rn.f32x2 %0, %1, %2, %3;" : "=l"(d) : "l"(a), "l"(b), "l"(c));
    return d;
}

__device__ __forceinline__ float bilin_g(const float* __restrict__ img, float sy, float sx) {
    float y0f = floorf(sy), x0f = floorf(sx);
    float wy = sy - y0f, wx = sx - x0f;
    int iy0 = (int)y0f, ix0 = (int)x0f;
    int iy1 = iy0 + 1, ix1 = ix0 + 1;
    bool y0ok = ((unsigned)iy0 < (unsigned)HH);
    bool y1ok = ((unsigned)iy1 < (unsigned)HH);
    bool x0ok = ((unsigned)ix0 < (unsigned)WW);
    bool x1ok = ((unsigned)ix1 < (unsigned)WW);
    int r0 = iy0 * WW;
    int r1 = iy1 * WW;
    float v00 = (y0ok && x0ok) ? img[r0 + ix0] : 0.f;
    float v01 = (y0ok && x1ok) ? img[r0 + ix1] : 0.f;
    float v10 = (y1ok && x0ok) ? img[r1 + ix0] : 0.f;
    float v11 = (y1ok && x1ok) ? img[r1 + ix1] : 0.f;
    return (1.f - wy) * ((1.f - wx) * v00 + wx * v01)
         +        wy  * ((1.f - wx) * v10 + wx * v11);
}

// ---------------------------------------------------------------------------
// Prep: 3x3 conv (8->24) via packed f32x2 FMA (2 vertical pixels / thread),
// tanh + conf-gated affinity normalization. Writes exact fp32 off/aff into
// d_out, 64B quantized record into g_rec, substituted field into g_feat[0].
// ---------------------------------------------------------------------------
__global__ void __launch_bounds__(256) prep_kernel(
    const float* __restrict__ guidance,
    const float* __restrict__ confidence,
    const float* __restrict__ feat_init,
    const float* __restrict__ feat_fix,
    const float* __restrict__ w_oa,
    const float* __restrict__ b_oa,
    const float* __restrict__ ascale,
    float* __restrict__ out_off,
    float* __restrict__ out_aff)
{
    __shared__ ulonglong2 swp2[864];     // weights duplicated {w,w}
    __shared__ float sb[24];
    {
        float2* swf = (float2*)swp2;
        for (int i = threadIdx.x; i < 1728; i += 256) {
            int oc = i / 72, r = i % 72;        // r = ic*9 + ky*3 + kx
            float w = w_oa[i];
            swf[r * 24 + oc] = make_float2(w, w);
        }
        if (threadIdx.x < 24) sb[threadIdx.x] = b_oa[threadIdx.x];
    }
    __syncthreads();

    int t = blockIdx.x * 256 + threadIdx.x;
    if (t >= BB * 120 * WW) return;
    int x  = t % WW;
    int yg = (t / WW) % 120;
    int b  = t / (WW * 120);
    int y0 = yg * 2;

    unsigned long long acc2[24];
    #pragma unroll
    for (int oc = 0; oc < 24; oc++) acc2[oc] = pk2(sb[oc], sb[oc]);

    const float* gb = guidance + (size_t)b * 8 * HWc;

    #pragma unroll 1
    for (int ic = 0; ic < 8; ic++) {
        const float* gi = gb + (size_t)ic * HWc;
        #pragma unroll
        for (int ky = 0; ky < 3; ky++) {
            int yy0 = y0 + ky - 1;
            int yy1 = yy0 + 1;
            bool r0 = ((unsigned)yy0 < (unsigned)HH);
            bool r1 = ((unsigned)yy1 < (unsigned)HH);
            #pragma unroll
            for (int kx = 0; kx < 3; kx++) {
                int xx = x + kx - 1;
                bool xo = ((unsigned)xx < (unsigned)WW);
                float g0 = (r0 && xo) ? gi[yy0 * WW + xx] : 0.f;
                float g1 = (r1 && xo) ? gi[yy1 * WW + xx] : 0.f;
                unsigned long long g2 = pk2(g0, g1);
                const ulonglong2* wv = swp2 + (ic * 9 + ky * 3 + kx) * 12;
                #pragma unroll
                for (int q = 0; q < 12; q++) {
                    ulonglong2 w = wv[q];
                    acc2[2*q]   = ffma2(w.x, g2, acc2[2*q]);
                    acc2[2*q+1] = ffma2(w.y, g2, acc2[2*q+1]);
                }
            }
        }
    }

    float inv_s = 1.f / (ascale[0] + 1e-8f);
    const float* conf = confidence + (size_t)b * HWc;

    #pragma unroll 1
    for (int s = 0; s < 2; s++) {
        int y = y0 + s;
        int rem = y * WW + x;

        float A[24];
        #pragma unroll
        for (int j = 0; j < 24; j++) {
            float2 f = unpk2(acc2[j]);
            A[j] = s ? f.y : f.x;
        }

        float av[8];
        #pragma unroll
        for (int j = 0; j < 8; j++) {
            float a  = tanhf(A[16 + j]) * inv_s;
            float ca = bilin_g(conf, (float)y + A[2*j], (float)x + A[2*j + 1]);
            av[j] = a * ca;
        }
        float ssum = 1e-4f;
        #pragma unroll
        for (int j = 0; j < 8; j++) ssum += fabsf(av[j]);
        ssum = fmaxf(ssum, 1.f);
        float asum = 0.f;
        #pragma unroll
        for (int j = 0; j < 8; j++) { av[j] = av[j] / ssum; asum += av[j]; }
        float aref = 1.f - asum;

        // exact fp32 outputs
        size_t ob = (size_t)b * 18 * HWc + rem;
        #pragma unroll
        for (int n = 0; n < 9; n++) {
            float oy, ox;
            if (n < 4)       { oy = A[2*n];         ox = A[2*n + 1]; }
            else if (n == 4) { oy = 0.f;            ox = 0.f; }
            else             { oy = A[2*(n-1)];     ox = A[2*(n-1) + 1]; }
            out_off[ob + (size_t)(2*n)     * HWc] = oy;
            out_off[ob + (size_t)(2*n + 1) * HWc] = ox;
        }
        size_t ab = (size_t)b * 9 * HWc + rem;
        #pragma unroll
        for (int n = 0; n < 9; n++) {
            float a = (n < 4) ? av[n] : (n == 4 ? aref : av[n - 1]);
            out_aff[ab + (size_t)n * HWc] = a;
        }

        int pidx = b * HWc + rem;
        float fx = feat_fix[pidx];

        // 64B quantized record
        union { Rec r; int4 v[4]; } u;
        #pragma unroll
        for (int k = 0; k < 8; k++) {
            int qy = __float2int_rn(A[2*k]     * 4096.f);
            int qx = __float2int_rn(A[2*k + 1] * 4096.f);
            qy = max(-32767, min(32767, qy));
            qx = max(-32767, min(32767, qx));
            u.r.off[k] = make_short2((short)qy, (short)qx);
        }
        #pragma unroll
        for (int j = 0; j < 8; j++) {
            int q = __float2int_rn(av[j] * 16384.f);
            q = max(-32767, min(32767, q));
            u.r.affq[j] = (short)q;
        }
        u.r.acen = aref;
        u.r.fix  = fx;
        int4* rp = (int4*)&g_rec[pidx];
        rp[0] = u.v[0]; rp[1] = u.v[1]; rp[2] = u.v[2]; rp[3] = u.v[3];

        g_feat[0][pidx] = (fx > 0.f) ? fx : feat_init[pidx];
    }
}

// ---------------------------------------------------------------------------
// One propagation step, pair-tiled smem. Block = 16 rows x 64 cols useful
// (4 px per thread). Tile stored as float2 horizontal pairs:
//   tp2[r][c] = { feat[r][c], feat[r][c+1] }
// so each bilinear tap needs only 2 x LDS.64 (row pairs) instead of 4 scalar
// LDS. Zero-filled out-of-image border; rare out-of-tile samples fall back
// to exact global bilinear.
// ---------------------------------------------------------------------------
#define TROWS 32
#define TCOLS 80

__global__ void __launch_bounds__(256, 5) prop_kernel(
    int ibuf, float* __restrict__ dout_feat, int last)
{
    __shared__ float2 tp2[TROWS * TCOLS];

    int b   = blockIdx.z;
    int y0  = blockIdx.y * 16;
    int cx0 = blockIdx.x * 64;
    int ry0 = y0 - 8;
    int cxl = cx0 - 8;

    const float* __restrict__ fp = &g_feat[ibuf][b * HWc];

    // fill pair tile: 2560 pairs, 2 cached LDG each
    #pragma unroll
    for (int i = threadIdx.x; i < TROWS * TCOLS; i += 256) {
        int r = i / TCOLS, c = i - r * TCOLS;
        int gy = ry0 + r;
        int gx0 = cxl + c;
        float v0 = 0.f, v1 = 0.f;
        if ((unsigned)gy < (unsigned)HH) {
            const float* row = fp + gy * WW;
            if ((unsigned)gx0 < (unsigned)WW)       v0 = row[gx0];
            if ((unsigned)(gx0 + 1) < (unsigned)WW) v1 = row[gx0 + 1];
        }
        tp2[i] = make_float2(v0, v1);
    }
    __syncthreads();

    int lx  = threadIdx.x & 63;       // 0..63
    int lyg = threadIdx.x >> 6;       // 0..3
    int gx  = cx0 + lx;

    const float Qo = 1.f / 4096.f;
    const float Qa = 1.f / 16384.f;

    #pragma unroll
    for (int i = 0; i < 4; i++) {
        int rr   = lyg * 4 + i;       // useful-row index 0..15
        int y    = y0 + rr;
        int rem  = y * WW + gx;
        int pidx = b * HWc + rem;

        union { Rec r; int4 v[4]; } u;
        const int4* rp = (const int4*)&g_rec[pidx];
        u.v[0] = rp[0]; u.v[1] = rp[1]; u.v[2] = rp[2]; u.v[3] = rp[3];

        // center tap: exact fp32 affinity, offset exactly zero
        float sum = u.r.acen * tp2[(rr + 8) * TCOLS + lx + 8].x;

        #pragma unroll
        for (int k = 0; k < 9; k++) {
            if (k == 4) continue;
            int j = (k < 4) ? k : k - 1;
            float a  = (float)u.r.affq[j] * Qa;
            float oy = (float)u.r.off[j].x * Qo;
            float ox = (float)u.r.off[j].y * Qo;
            float sy = (float)(rr + 8 + (k / 3) - 1) + oy;   // tile-local
            float sx = (float)(lx + 8 + (k % 3) - 1) + ox;
            float fy = floorf(sy), fxx = floorf(sx);
            int   iy = (int)fy,    ix  = (int)fxx;
            float wy = sy - fy,    wx  = sx - fxx;
            float v;
            if (((unsigned)iy < (unsigned)(TROWS - 1)) &&
                ((unsigned)ix < (unsigned)(TCOLS - 1))) {
                float2 t0 = tp2[iy * TCOLS + ix];          // v00, v01
                float2 t1 = tp2[iy * TCOLS + ix + TCOLS];  // v10, v11
                float v0 = fmaf(wx, t0.y - t0.x, t0.x);
                float v1 = fmaf(wx, t1.y - t1.x, t1.x);
                v = fmaf(wy, v1 - v0, v0);
            } else {
                v = bilin_g(fp, sy + (float)ry0, sx + (float)cxl);
            }
            sum = fmaf(a, v, sum);
        }

        if (last) {
            dout_feat[pidx] = sum;
        } else {
            float fx = u.r.fix;
            g_feat[1 - ibuf][pidx] = (fx > 0.f) ? fx : sum;
        }
    }
}

extern "C" void kernel_launch(void* const* d_in, const int* in_sizes, int n_in,
                              void* d_out, int out_size) {
    const float* feat_init  = (const float*)d_in[0];
    const float* guidance   = (const float*)d_in[1];
    const float* confidence = (const float*)d_in[2];
    const float* feat_fix   = (const float*)d_in[3];
    const float* w_oa       = (const float*)d_in[4];
    const float* b_oa       = (const float*)d_in[5];
    const float* ascale     = (const float*)d_in[6];

    float* out      = (float*)d_out;
    float* out_feat = out;                         // B*1*H*W
    float* out_off  = out + (size_t)NPX;           // B*18*H*W
    float* out_aff  = out + (size_t)NPX * 19;      // B*9*H*W

    prep_kernel<<<(BB * 120 * WW + 255) / 256, 256>>>(
        guidance, confidence, feat_init, feat_fix, w_oa, b_oa, ascale,
        out_off, out_aff);

    dim3 pgrid(WW / 64, HH / 16, BB);              // 19 x 15 x 4 = 1140
    for (int it = 0; it < 18; ++it) {
        prop_kernel<<<pgrid, 256>>>(it & 1, out_feat, it == 17);
    }
}

// round 7
// speedup vs baseline: 1.0073x; 1.0073x over previous
#include <cuda_runtime.h>
#include <math.h>

#define BB  4
#define HH  240
#define WW  1216
#define HWc (HH*WW)          // 291840
#define NPX (BB*HWc)         // 1167360

// ping-pong feature buffers (substituted field)
__device__ float g_feat[2][NPX];

// 64B per-pixel record
struct alignas(16) Rec {
    short2 off[8];    // taps 0..3,5..8 offsets, s3.12
    short  affq[8];   // taps 0..3,5..8 affinities, s1.14 (Q=16384)
    float  acen;      // exact fp32 center affinity
    float  fix;       // feat_fix value
};
__device__ Rec g_rec[NPX];

// ---------------- f32x2 helpers (Blackwell packed fp32 pipe) ----------------
__device__ __forceinline__ unsigned long long pk2(float lo, float hi) {
    unsigned long long r;
    asm("mov.b64 %0, {%1,%2};" : "=l"(r) : "f"(lo), "f"(hi));
    return r;
}
__device__ __forceinline__ float2 unpk2(unsigned long long v) {
    float2 f;
    asm("mov.b64 {%0,%1}, %2;" : "=f"(f.x), "=f"(f.y) : "l"(v));
    return f;
}
__device__ __forceinline__ unsigned long long ffma2(unsigned long long a,
                                                    unsigned long long b,
                                                    unsigned long long c) {
    unsigned long long d;
    asm("fma.rn.f32x2 %0, %1, %2, %3;" : "=l"(d) : "l"(a), "l"(b), "l"(c));
    return d;
}

__device__ __forceinline__ float bilin_g(const float* __restrict__ img, float sy, float sx) {
    float y0f = floorf(sy), x0f = floorf(sx);
    float wy = sy - y0f, wx = sx - x0f;
    int iy0 = (int)y0f, ix0 = (int)x0f;
    int iy1 = iy0 + 1, ix1 = ix0 + 1;
    bool y0ok = ((unsigned)iy0 < (unsigned)HH);
    bool y1ok = ((unsigned)iy1 < (unsigned)HH);
    bool x0ok = ((unsigned)ix0 < (unsigned)WW);
    bool x1ok = ((unsigned)ix1 < (unsigned)WW);
    int r0 = iy0 * WW;
    int r1 = iy1 * WW;
    float v00 = (y0ok && x0ok) ? img[r0 + ix0] : 0.f;
    float v01 = (y0ok && x1ok) ? img[r0 + ix1] : 0.f;
    float v10 = (y1ok && x0ok) ? img[r1 + ix0] : 0.f;
    float v11 = (y1ok && x1ok) ? img[r1 + ix1] : 0.f;
    return (1.f - wy) * ((1.f - wx) * v00 + wx * v01)
         +        wy  * ((1.f - wx) * v10 + wx * v11);
}

// ---------------------------------------------------------------------------
// Prep: 3x3 conv (8->24) via packed f32x2 FMA (2 vertical pixels / thread),
// tanh + conf-gated affinity normalization. Writes exact fp32 off/aff into
// d_out, 64B quantized record into g_rec, substituted field into g_feat[0].
// ---------------------------------------------------------------------------
__global__ void __launch_bounds__(256) prep_kernel(
    const float* __restrict__ guidance,
    const float* __restrict__ confidence,
    const float* __restrict__ feat_init,
    const float* __restrict__ feat_fix,
    const float* __restrict__ w_oa,
    const float* __restrict__ b_oa,
    const float* __restrict__ ascale,
    float* __restrict__ out_off,
    float* __restrict__ out_aff)
{
    __shared__ ulonglong2 swp2[864];     // weights duplicated {w,w}
    __shared__ float sb[24];
    {
        float2* swf = (float2*)swp2;
        for (int i = threadIdx.x; i < 1728; i += 256) {
            int oc = i / 72, r = i % 72;        // r = ic*9 + ky*3 + kx
            float w = w_oa[i];
            swf[r * 24 + oc] = make_float2(w, w);
        }
        if (threadIdx.x < 24) sb[threadIdx.x] = b_oa[threadIdx.x];
    }
    __syncthreads();

    int t = blockIdx.x * 256 + threadIdx.x;
    if (t >= BB * 120 * WW) return;
    int x  = t % WW;
    int yg = (t / WW) % 120;
    int b  = t / (WW * 120);
    int y0 = yg * 2;

    unsigned long long acc2[24];
    #pragma unroll
    for (int oc = 0; oc < 24; oc++) acc2[oc] = pk2(sb[oc], sb[oc]);

    const float* gb = guidance + (size_t)b * 8 * HWc;

    #pragma unroll 1
    for (int ic = 0; ic < 8; ic++) {
        const float* gi = gb + (size_t)ic * HWc;
        #pragma unroll
        for (int ky = 0; ky < 3; ky++) {
            int yy0 = y0 + ky - 1;
            int yy1 = yy0 + 1;
            bool r0 = ((unsigned)yy0 < (unsigned)HH);
            bool r1 = ((unsigned)yy1 < (unsigned)HH);
            #pragma unroll
            for (int kx = 0; kx < 3; kx++) {
                int xx = x + kx - 1;
                bool xo = ((unsigned)xx < (unsigned)WW);
                float g0 = (r0 && xo) ? gi[yy0 * WW + xx] : 0.f;
                float g1 = (r1 && xo) ? gi[yy1 * WW + xx] : 0.f;
                unsigned long long g2 = pk2(g0, g1);
                const ulonglong2* wv = swp2 + (ic * 9 + ky * 3 + kx) * 12;
                #pragma unroll
                for (int q = 0; q < 12; q++) {
                    ulonglong2 w = wv[q];
                    acc2[2*q]   = ffma2(w.x, g2, acc2[2*q]);
                    acc2[2*q+1] = ffma2(w.y, g2, acc2[2*q+1]);
                }
            }
        }
    }

    float inv_s = 1.f / (ascale[0] + 1e-8f);
    const float* conf = confidence + (size_t)b * HWc;

    #pragma unroll 1
    for (int s = 0; s < 2; s++) {
        int y = y0 + s;
        int rem = y * WW + x;

        float A[24];
        #pragma unroll
        for (int j = 0; j < 24; j++) {
            float2 f = unpk2(acc2[j]);
            A[j] = s ? f.y : f.x;
        }

        float av[8];
        #pragma unroll
        for (int j = 0; j < 8; j++) {
            float a  = tanhf(A[16 + j]) * inv_s;
            float ca = bilin_g(conf, (float)y + A[2*j], (float)x + A[2*j + 1]);
            av[j] = a * ca;
        }
        float ssum = 1e-4f;
        #pragma unroll
        for (int j = 0; j < 8; j++) ssum += fabsf(av[j]);
        ssum = fmaxf(ssum, 1.f);
        float asum = 0.f;
        #pragma unroll
        for (int j = 0; j < 8; j++) { av[j] = av[j] / ssum; asum += av[j]; }
        float aref = 1.f - asum;

        // exact fp32 outputs
        size_t ob = (size_t)b * 18 * HWc + rem;
        #pragma unroll
        for (int n = 0; n < 9; n++) {
            float oy, ox;
            if (n < 4)       { oy = A[2*n];         ox = A[2*n + 1]; }
            else if (n == 4) { oy = 0.f;            ox = 0.f; }
            else             { oy = A[2*(n-1)];     ox = A[2*(n-1) + 1]; }
            out_off[ob + (size_t)(2*n)     * HWc] = oy;
            out_off[ob + (size_t)(2*n + 1) * HWc] = ox;
        }
        size_t ab = (size_t)b * 9 * HWc + rem;
        #pragma unroll
        for (int n = 0; n < 9; n++) {
            float a = (n < 4) ? av[n] : (n == 4 ? aref : av[n - 1]);
            out_aff[ab + (size_t)n * HWc] = a;
        }

        int pidx = b * HWc + rem;
        float fx = feat_fix[pidx];

        // 64B quantized record
        union { Rec r; int4 v[4]; } u;
        #pragma unroll
        for (int k = 0; k < 8; k++) {
            int qy = __float2int_rn(A[2*k]     * 4096.f);
            int qx = __float2int_rn(A[2*k + 1] * 4096.f);
            qy = max(-32767, min(32767, qy));
            qx = max(-32767, min(32767, qx));
            u.r.off[k] = make_short2((short)qy, (short)qx);
        }
        #pragma unroll
        for (int j = 0; j < 8; j++) {
            int q = __float2int_rn(av[j] * 16384.f);
            q = max(-32767, min(32767, q));
            u.r.affq[j] = (short)q;
        }
        u.r.acen = aref;
        u.r.fix  = fx;
        int4* rp = (int4*)&g_rec[pidx];
        rp[0] = u.v[0]; rp[1] = u.v[1]; rp[2] = u.v[2]; rp[3] = u.v[3];

        g_feat[0][pidx] = (fx > 0.f) ? fx : feat_init[pidx];
    }
}

// ---------------------------------------------------------------------------
// One propagation step, smem-tiled. Block = 12 rows x 64 cols useful (3 px
// per thread), tile = 28x80 scalar floats with zero-filled out-of-image
// border. Grid = 19x20x4 = 1520 blocks = 2.05 waves at occ 5 (kills the
// 1.54-wave tail of the 16-row tiling). Rare out-of-tile samples fall back
// to exact global bilinear.
// ---------------------------------------------------------------------------
#define TROWS 28
#define TCOLS 80

__global__ void __launch_bounds__(256, 5) prop_kernel(
    int ibuf, float* __restrict__ dout_feat, int last)
{
    __shared__ float tile[TROWS * TCOLS];

    int b   = blockIdx.z;
    int y0  = blockIdx.y * 12;
    int cx0 = blockIdx.x * 64;
    int ry0 = y0 - 8;
    int cxl = cx0 - 8;

    const float* __restrict__ fp = &g_feat[ibuf][b * HWc];

    #pragma unroll
    for (int i = threadIdx.x; i < TROWS * TCOLS; i += 256) {
        int r = i / TCOLS, c = i - r * TCOLS;
        int gy = ry0 + r, gx = cxl + c;
        float v = 0.f;
        if (((unsigned)gy < (unsigned)HH) && ((unsigned)gx < (unsigned)WW))
            v = fp[gy * WW + gx];
        tile[i] = v;
    }
    __syncthreads();

    int lx  = threadIdx.x & 63;       // 0..63
    int lyg = threadIdx.x >> 6;       // 0..3
    int gx  = cx0 + lx;

    const float Qo = 1.f / 4096.f;
    const float Qa = 1.f / 16384.f;

    #pragma unroll
    for (int i = 0; i < 3; i++) {
        int rr   = lyg * 3 + i;       // useful-row index 0..11
        int y    = y0 + rr;
        int rem  = y * WW + gx;
        int pidx = b * HWc + rem;

        union { Rec r; int4 v[4]; } u;
        const int4* rp = (const int4*)&g_rec[pidx];
        u.v[0] = rp[0]; u.v[1] = rp[1]; u.v[2] = rp[2]; u.v[3] = rp[3];

        // center tap: exact fp32 affinity, offset exactly zero
        float sum = u.r.acen * tile[(rr + 8) * TCOLS + lx + 8];

        #pragma unroll
        for (int k = 0; k < 9; k++) {
            if (k == 4) continue;
            int j = (k < 4) ? k : k - 1;
            float a  = (float)u.r.affq[j] * Qa;
            float oy = (float)u.r.off[j].x * Qo;
            float ox = (float)u.r.off[j].y * Qo;
            float sy = (float)(rr + 8 + (k / 3) - 1) + oy;   // tile-local
            float sx = (float)(lx + 8 + (k % 3) - 1) + ox;
            float fy = floorf(sy), fxx = floorf(sx);
            int   iy = (int)fy,    ix  = (int)fxx;
            float wy = sy - fy,    wx  = sx - fxx;
            float v;
            if (((unsigned)iy < (unsigned)(TROWS - 1)) &&
                ((unsigned)ix < (unsigned)(TCOLS - 1))) {
                const float* tp = &tile[iy * TCOLS + ix];
                float v00 = tp[0],     v01 = tp[1];
                float v10 = tp[TCOLS], v11 = tp[TCOLS + 1];
                float v0 = fmaf(wx, v01 - v00, v00);
                float v1 = fmaf(wx, v11 - v10, v10);
                v = fmaf(wy, v1 - v0, v0);
            } else {
                v = bilin_g(fp, sy + (float)ry0, sx + (float)cxl);
            }
            sum = fmaf(a, v, sum);
        }

        if (last) {
            dout_feat[pidx] = sum;
        } else {
            float fx = u.r.fix;
            g_feat[1 - ibuf][pidx] = (fx > 0.f) ? fx : sum;
        }
    }
}

extern "C" void kernel_launch(void* const* d_in, const int* in_sizes, int n_in,
                              void* d_out, int out_size) {
    const float* feat_init  = (const float*)d_in[0];
    const float* guidance   = (const float*)d_in[1];
    const float* confidence = (const float*)d_in[2];
    const float* feat_fix   = (const float*)d_in[3];
    const float* w_oa       = (const float*)d_in[4];
    const float* b_oa       = (const float*)d_in[5];
    const float* ascale     = (const float*)d_in[6];

    float* out      = (float*)d_out;
    float* out_feat = out;                         // B*1*H*W
    float* out_off  = out + (size_t)NPX;           // B*18*H*W
    float* out_aff  = out + (size_t)NPX * 19;      // B*9*H*W

    prep_kernel<<<(BB * 120 * WW + 255) / 256, 256>>>(
        guidance, confidence, feat_init, feat_fix, w_oa, b_oa, ascale,
        out_off, out_aff);

    dim3 pgrid(WW / 64, HH / 12, BB);              // 19 x 20 x 4 = 1520
    for (int it = 0; it < 18; ++it) {
        prop_kernel<<<pgrid, 256>>>(it & 1, out_feat, it == 17);
    }
}

// round 9
// speedup vs baseline: 1.1099x; 1.1019x over previous
#include <cuda_runtime.h>
#include <math.h>

#define BB  4
#define HH  240
#define WW  1216
#define HWc (HH*WW)          // 291840
#define NPX (BB*HWc)         // 1167360

// ping-pong feature buffers (substituted field)
__device__ float g_feat[2][NPX];

// 64B per-pixel record (64B-aligned so 32B v4.b64 loads are legal)
struct alignas(64) Rec {
    short2 off[8];    // taps 0..3,5..8 offsets, s3.12
    short  affq[8];   // taps 0..3,5..8 affinities, s1.14 (Q=16384)
    float  acen;      // exact fp32 center affinity
    float  fix;       // feat_fix value
};
__device__ Rec g_rec[NPX];

// ---------------- f32x2 helpers (Blackwell packed fp32 pipe) ----------------
__device__ __forceinline__ unsigned long long pk2(float lo, float hi) {
    unsigned long long r;
    asm("mov.b64 %0, {%1,%2};" : "=l"(r) : "f"(lo), "f"(hi));
    return r;
}
__device__ __forceinline__ float2 unpk2(unsigned long long v) {
    float2 f;
    asm("mov.b64 {%0,%1}, %2;" : "=f"(f.x), "=f"(f.y) : "l"(v));
    return f;
}
__device__ __forceinline__ unsigned long long ffma2(unsigned long long a,
                                                    unsigned long long b,
                                                    unsigned long long c) {
    unsigned long long d;
    asm("fma.rn.f32x2 %0, %1, %2, %3;" : "=l"(d) : "l"(a), "l"(b), "l"(c));
    return d;
}

// L2-pinned 32B load (sm_103a: evict_last requires v8.b32 / v4.b64)
__device__ __forceinline__ void ldg_el32(const void* p, unsigned long long* r) {
    asm("ld.global.nc.L2::evict_last.v4.b64 {%0,%1,%2,%3}, [%4];"
        : "=l"(r[0]), "=l"(r[1]), "=l"(r[2]), "=l"(r[3]) : "l"(p));
}

__device__ __forceinline__ float bilin_g(const float* __restrict__ img, float sy, float sx) {
    float y0f = floorf(sy), x0f = floorf(sx);
    float wy = sy - y0f, wx = sx - x0f;
    int iy0 = (int)y0f, ix0 = (int)x0f;
    int iy1 = iy0 + 1, ix1 = ix0 + 1;
    bool y0ok = ((unsigned)iy0 < (unsigned)HH);
    bool y1ok = ((unsigned)iy1 < (unsigned)HH);
    bool x0ok = ((unsigned)ix0 < (unsigned)WW);
    bool x1ok = ((unsigned)ix1 < (unsigned)WW);
    int r0 = iy0 * WW;
    int r1 = iy1 * WW;
    float v00 = (y0ok && x0ok) ? img[r0 + ix0] : 0.f;
    float v01 = (y0ok && x1ok) ? img[r0 + ix1] : 0.f;
    float v10 = (y1ok && x0ok) ? img[r1 + ix0] : 0.f;
    float v11 = (y1ok && x1ok) ? img[r1 + ix1] : 0.f;
    return (1.f - wy) * ((1.f - wx) * v00 + wx * v01)
         +        wy  * ((1.f - wx) * v10 + wx * v11);
}

// ---------------------------------------------------------------------------
// Prep: 3x3 conv (8->24) via packed f32x2 FMA (2 vertical pixels / thread),
// tanh + conf-gated affinity normalization. Writes exact fp32 off/aff into
// d_out with streaming stores (never re-read -> keep them out of L2), the
// 64B quantized record into g_rec, substituted field into g_feat[0].
// ---------------------------------------------------------------------------
__global__ void __launch_bounds__(256) prep_kernel(
    const float* __restrict__ guidance,
    const float* __restrict__ confidence,
    const float* __restrict__ feat_init,
    const float* __restrict__ feat_fix,
    const float* __restrict__ w_oa,
    const float* __restrict__ b_oa,
    const float* __restrict__ ascale,
    float* __restrict__ out_off,
    float* __restrict__ out_aff)
{
    __shared__ ulonglong2 swp2[864];     // weights duplicated {w,w}
    __shared__ float sb[24];
    {
        float2* swf = (float2*)swp2;
        for (int i = threadIdx.x; i < 1728; i += 256) {
            int oc = i / 72, r = i % 72;        // r = ic*9 + ky*3 + kx
            float w = w_oa[i];
            swf[r * 24 + oc] = make_float2(w, w);
        }
        if (threadIdx.x < 24) sb[threadIdx.x] = b_oa[threadIdx.x];
    }
    __syncthreads();

    int t = blockIdx.x * 256 + threadIdx.x;
    if (t >= BB * 120 * WW) return;
    int x  = t % WW;
    int yg = (t / WW) % 120;
    int b  = t / (WW * 120);
    int y0 = yg * 2;

    unsigned long long acc2[24];
    #pragma unroll
    for (int oc = 0; oc < 24; oc++) acc2[oc] = pk2(sb[oc], sb[oc]);

    const float* gb = guidance + (size_t)b * 8 * HWc;

    #pragma unroll 1
    for (int ic = 0; ic < 8; ic++) {
        const float* gi = gb + (size_t)ic * HWc;
        #pragma unroll
        for (int ky = 0; ky < 3; ky++) {
            int yy0 = y0 + ky - 1;
            int yy1 = yy0 + 1;
            bool r0 = ((unsigned)yy0 < (unsigned)HH);
            bool r1 = ((unsigned)yy1 < (unsigned)HH);
            #pragma unroll
            for (int kx = 0; kx < 3; kx++) {
                int xx = x + kx - 1;
                bool xo = ((unsigned)xx < (unsigned)WW);
                float g0 = (r0 && xo) ? gi[yy0 * WW + xx] : 0.f;
                float g1 = (r1 && xo) ? gi[yy1 * WW + xx] : 0.f;
                unsigned long long g2 = pk2(g0, g1);
                const ulonglong2* wv = swp2 + (ic * 9 + ky * 3 + kx) * 12;
                #pragma unroll
                for (int q = 0; q < 12; q++) {
                    ulonglong2 w = wv[q];
                    acc2[2*q]   = ffma2(w.x, g2, acc2[2*q]);
                    acc2[2*q+1] = ffma2(w.y, g2, acc2[2*q+1]);
                }
            }
        }
    }

    float inv_s = 1.f / (ascale[0] + 1e-8f);
    const float* conf = confidence + (size_t)b * HWc;

    #pragma unroll 1
    for (int s = 0; s < 2; s++) {
        int y = y0 + s;
        int rem = y * WW + x;

        float A[24];
        #pragma unroll
        for (int j = 0; j < 24; j++) {
            float2 f = unpk2(acc2[j]);
            A[j] = s ? f.y : f.x;
        }

        float av[8];
        #pragma unroll
        for (int j = 0; j < 8; j++) {
            float a  = tanhf(A[16 + j]) * inv_s;
            float ca = bilin_g(conf, (float)y + A[2*j], (float)x + A[2*j + 1]);
            av[j] = a * ca;
        }
        float ssum = 1e-4f;
        #pragma unroll
        for (int j = 0; j < 8; j++) ssum += fabsf(av[j]);
        ssum = fmaxf(ssum, 1.f);
        float asum = 0.f;
        #pragma unroll
        for (int j = 0; j < 8; j++) { av[j] = av[j] / ssum; asum += av[j]; }
        float aref = 1.f - asum;

        // exact fp32 outputs (streaming: never read again this launch)
        size_t ob = (size_t)b * 18 * HWc + rem;
        #pragma unroll
        for (int n = 0; n < 9; n++) {
            float oy, ox;
            if (n < 4)       { oy = A[2*n];         ox = A[2*n + 1]; }
            else if (n == 4) { oy = 0.f;            ox = 0.f; }
            else             { oy = A[2*(n-1)];     ox = A[2*(n-1) + 1]; }
            __stcs(&out_off[ob + (size_t)(2*n)     * HWc], oy);
            __stcs(&out_off[ob + (size_t)(2*n + 1) * HWc], ox);
        }
        size_t ab = (size_t)b * 9 * HWc + rem;
        #pragma unroll
        for (int n = 0; n < 9; n++) {
            float a = (n < 4) ? av[n] : (n == 4 ? aref : av[n - 1]);
            __stcs(&out_aff[ab + (size_t)n * HWc], a);
        }

        int pidx = b * HWc + rem;
        float fx = feat_fix[pidx];

        // 64B quantized record
        union { Rec r; int4 v[4]; } u;
        #pragma unroll
        for (int k = 0; k < 8; k++) {
            int qy = __float2int_rn(A[2*k]     * 4096.f);
            int qx = __float2int_rn(A[2*k + 1] * 4096.f);
            qy = max(-32767, min(32767, qy));
            qx = max(-32767, min(32767, qx));
            u.r.off[k] = make_short2((short)qy, (short)qx);
        }
        #pragma unroll
        for (int j = 0; j < 8; j++) {
            int q = __float2int_rn(av[j] * 16384.f);
            q = max(-32767, min(32767, q));
            u.r.affq[j] = (short)q;
        }
        u.r.acen = aref;
        u.r.fix  = fx;
        int4* rp = (int4*)&g_rec[pidx];
        rp[0] = u.v[0]; rp[1] = u.v[1]; rp[2] = u.v[2]; rp[3] = u.v[3];

        g_feat[0][pidx] = (fx > 0.f) ? fx : feat_init[pidx];
    }
}

// ---------------------------------------------------------------------------
// One propagation step, smem-tiled. Block = 16 rows x 64 cols useful (4 px
// per thread), tile = 27x75 (halo -5/+6: offsets are ~N(0,0.85^2) so |off|>4
// is ~5-sigma; those samples take the exact global fallback). Records are
// prefetched (px0 before the fill barrier, px i+1 during px i's compute) and
// loaded as 2 x 32B v4.b64 with L2::evict_last so the 75MB record array
// stays L2-resident across all 18 iterations.
// ---------------------------------------------------------------------------
#define TROWS 27
#define TCOLS 75

__global__ void __launch_bounds__(256, 5) prop_kernel(
    int ibuf, float* __restrict__ dout_feat, int last)
{
    __shared__ float tile[TROWS * TCOLS];

    int b   = blockIdx.z;
    int y0  = blockIdx.y * 16;
    int cx0 = blockIdx.x * 64;
    int ry0 = y0 - 5;
    int cxl = cx0 - 5;

    const float* __restrict__ fp = &g_feat[ibuf][b * HWc];

    int lx  = threadIdx.x & 63;       // 0..63
    int lyg = threadIdx.x >> 6;       // 0..3
    int gx  = cx0 + lx;

    // prefetch px0's record before the fill barrier
    int pidx0 = b * HWc + (y0 + lyg * 4) * WW + gx;
    union RecU { Rec r; unsigned long long v[8]; };
    RecU cur, nxt;
    {
        const char* rp = (const char*)&g_rec[pidx0];
        ldg_el32(rp,      &cur.v[0]);
        ldg_el32(rp + 32, &cur.v[4]);
    }

    #pragma unroll
    for (int i = threadIdx.x; i < TROWS * TCOLS; i += 256) {
        int r = i / TCOLS, c = i - r * TCOLS;
        int gy = ry0 + r, gxx = cxl + c;
        float v = 0.f;
        if (((unsigned)gy < (unsigned)HH) && ((unsigned)gxx < (unsigned)WW))
            v = fp[gy * WW + gxx];
        tile[i] = v;
    }
    __syncthreads();

    const float Qo = 1.f / 4096.f;
    const float Qa = 1.f / 16384.f;

    #pragma unroll
    for (int i = 0; i < 4; i++) {
        int rr   = lyg * 4 + i;       // useful-row index 0..15
        int pidx = pidx0 + i * WW;

        // prefetch next px's record while computing this one
        if (i < 3) {
            const char* rp = (const char*)&g_rec[pidx + WW];
            ldg_el32(rp,      &nxt.v[0]);
            ldg_el32(rp + 32, &nxt.v[4]);
        }

        // center tap: exact fp32 affinity, offset exactly zero
        float sum = cur.r.acen * tile[(rr + 5) * TCOLS + lx + 5];

        #pragma unroll
        for (int k = 0; k < 9; k++) {
            if (k == 4) continue;
            int j = (k < 4) ? k : k - 1;
            float a  = (float)cur.r.affq[j] * Qa;
            float oy = (float)cur.r.off[j].x * Qo;
            float ox = (float)cur.r.off[j].y * Qo;
            float sy = (float)(rr + 5 + (k / 3) - 1) + oy;   // tile-local
            float sx = (float)(lx + 5 + (k % 3) - 1) + ox;
            float fy = floorf(sy), fxx = floorf(sx);
            int   iy = (int)fy,    ix  = (int)fxx;
            float wy = sy - fy,    wx  = sx - fxx;
            float v;
            if (((unsigned)iy < (unsigned)(TROWS - 1)) &&
                ((unsigned)ix < (unsigned)(TCOLS - 1))) {
                const float* tp = &tile[iy * TCOLS + ix];
                float v00 = tp[0],     v01 = tp[1];
                float v10 = tp[TCOLS], v11 = tp[TCOLS + 1];
                float v0 = fmaf(wx, v01 - v00, v00);
                float v1 = fmaf(wx, v11 - v10, v10);
                v = fmaf(wy, v1 - v0, v0);
            } else {
                v = bilin_g(fp, sy + (float)ry0, sx + (float)cxl);
            }
            sum = fmaf(a, v, sum);
        }

        if (last) {
            __stcs(&dout_feat[pidx], sum);
        } else {
            float fx = cur.r.fix;
            g_feat[1 - ibuf][pidx] = (fx > 0.f) ? fx : sum;
        }

        #pragma unroll
        for (int q = 0; q < 8; q++) cur.v[q] = nxt.v[q];
    }
}

extern "C" void kernel_launch(void* const* d_in, const int* in_sizes, int n_in,
                              void* d_out, int out_size) {
    const float* feat_init  = (const float*)d_in[0];
    const float* guidance   = (const float*)d_in[1];
    const float* confidence = (const float*)d_in[2];
    const float* feat_fix   = (const float*)d_in[3];
    const float* w_oa       = (const float*)d_in[4];
    const float* b_oa       = (const float*)d_in[5];
    const float* ascale     = (const float*)d_in[6];

    float* out      = (float*)d_out;
    float* out_feat = out;                         // B*1*H*W
    float* out_off  = out + (size_t)NPX;           // B*18*H*W
    float* out_aff  = out + (size_t)NPX * 19;      // B*9*H*W

    prep_kernel<<<(BB * 120 * WW + 255) / 256, 256>>>(
        guidance, confidence, feat_init, feat_fix, w_oa, b_oa, ascale,
        out_off, out_aff);

    dim3 pgrid(WW / 64, HH / 16, BB);              // 19 x 15 x 4 = 1140
    for (int it = 0; it < 18; ++it) {
        prop_kernel<<<pgrid, 256>>>(it & 1, out_feat, it == 17);
    }
}

// round 10
// speedup vs baseline: 1.1382x; 1.0256x over previous
#include <cuda_runtime.h>
#include <math.h>

#define BB  4
#define HH  240
#define WW  1216
#define HWc (HH*WW)          // 291840
#define NPX (BB*HWc)         // 1167360

// ping-pong feature buffers (substituted field)
__device__ float g_feat[2][NPX];

// 64B per-pixel record (64B-aligned so 32B v4.b64 loads are legal)
struct alignas(64) Rec {
    short2 off[8];    // taps 0..3,5..8 offsets, s3.12
    short  affq[8];   // taps 0..3,5..8 affinities, s1.14 (Q=16384)
    float  acen;      // exact fp32 center affinity
    float  fix;       // feat_fix value
};
__device__ Rec g_rec[NPX];

// ---------------- f32x2 helpers (Blackwell packed fp32 pipe) ----------------
__device__ __forceinline__ unsigned long long pk2(float lo, float hi) {
    unsigned long long r;
    asm("mov.b64 %0, {%1,%2};" : "=l"(r) : "f"(lo), "f"(hi));
    return r;
}
__device__ __forceinline__ float2 unpk2(unsigned long long v) {
    float2 f;
    asm("mov.b64 {%0,%1}, %2;" : "=f"(f.x), "=f"(f.y) : "l"(v));
    return f;
}
__device__ __forceinline__ unsigned long long ffma2(unsigned long long a,
                                                    unsigned long long b,
                                                    unsigned long long c) {
    unsigned long long d;
    asm("fma.rn.f32x2 %0, %1, %2, %3;" : "=l"(d) : "l"(a), "l"(b), "l"(c));
    return d;
}

// 32B load with L2 evict_last (sm_103a wide-load form; also 2x fewer LDGs)
__device__ __forceinline__ void ldg_el32(const void* p, unsigned long long* r) {
    asm("ld.global.nc.L2::evict_last.v4.b64 {%0,%1,%2,%3}, [%4];"
        : "=l"(r[0]), "=l"(r[1]), "=l"(r[2]), "=l"(r[3]) : "l"(p));
}

__device__ __forceinline__ float bilin_g(const float* __restrict__ img, float sy, float sx) {
    float y0f = floorf(sy), x0f = floorf(sx);
    float wy = sy - y0f, wx = sx - x0f;
    int iy0 = (int)y0f, ix0 = (int)x0f;
    int iy1 = iy0 + 1, ix1 = ix0 + 1;
    bool y0ok = ((unsigned)iy0 < (unsigned)HH);
    bool y1ok = ((unsigned)iy1 < (unsigned)HH);
    bool x0ok = ((unsigned)ix0 < (unsigned)WW);
    bool x1ok = ((unsigned)ix1 < (unsigned)WW);
    int r0 = iy0 * WW;
    int r1 = iy1 * WW;
    float v00 = (y0ok && x0ok) ? img[r0 + ix0] : 0.f;
    float v01 = (y0ok && x1ok) ? img[r0 + ix1] : 0.f;
    float v10 = (y1ok && x0ok) ? img[r1 + ix0] : 0.f;
    float v11 = (y1ok && x1ok) ? img[r1 + ix1] : 0.f;
    return (1.f - wy) * ((1.f - wx) * v00 + wx * v01)
         +        wy  * ((1.f - wx) * v10 + wx * v11);
}

// ---------------------------------------------------------------------------
// Prep: 3x3 conv (8->24) via packed f32x2 FMA (2 vertical pixels / thread),
// tanh + conf-gated affinity normalization. Writes exact fp32 off/aff into
// d_out with streaming stores (never re-read -> keep them out of L2), the
// 64B quantized record into g_rec, substituted field into g_feat[0].
// ---------------------------------------------------------------------------
__global__ void __launch_bounds__(256) prep_kernel(
    const float* __restrict__ guidance,
    const float* __restrict__ confidence,
    const float* __restrict__ feat_init,
    const float* __restrict__ feat_fix,
    const float* __restrict__ w_oa,
    const float* __restrict__ b_oa,
    const float* __restrict__ ascale,
    float* __restrict__ out_off,
    float* __restrict__ out_aff)
{
    __shared__ ulonglong2 swp2[864];     // weights duplicated {w,w}
    __shared__ float sb[24];
    {
        float2* swf = (float2*)swp2;
        for (int i = threadIdx.x; i < 1728; i += 256) {
            int oc = i / 72, r = i % 72;        // r = ic*9 + ky*3 + kx
            float w = w_oa[i];
            swf[r * 24 + oc] = make_float2(w, w);
        }
        if (threadIdx.x < 24) sb[threadIdx.x] = b_oa[threadIdx.x];
    }
    __syncthreads();

    int t = blockIdx.x * 256 + threadIdx.x;
    if (t >= BB * 120 * WW) return;
    int x  = t % WW;
    int yg = (t / WW) % 120;
    int b  = t / (WW * 120);
    int y0 = yg * 2;

    unsigned long long acc2[24];
    #pragma unroll
    for (int oc = 0; oc < 24; oc++) acc2[oc] = pk2(sb[oc], sb[oc]);

    const float* gb = guidance + (size_t)b * 8 * HWc;

    #pragma unroll 1
    for (int ic = 0; ic < 8; ic++) {
        const float* gi = gb + (size_t)ic * HWc;
        #pragma unroll
        for (int ky = 0; ky < 3; ky++) {
            int yy0 = y0 + ky - 1;
            int yy1 = yy0 + 1;
            bool r0 = ((unsigned)yy0 < (unsigned)HH);
            bool r1 = ((unsigned)yy1 < (unsigned)HH);
            #pragma unroll
            for (int kx = 0; kx < 3; kx++) {
                int xx = x + kx - 1;
                bool xo = ((unsigned)xx < (unsigned)WW);
                float g0 = (r0 && xo) ? gi[yy0 * WW + xx] : 0.f;
                float g1 = (r1 && xo) ? gi[yy1 * WW + xx] : 0.f;
                unsigned long long g2 = pk2(g0, g1);
                const ulonglong2* wv = swp2 + (ic * 9 + ky * 3 + kx) * 12;
                #pragma unroll
                for (int q = 0; q < 12; q++) {
                    ulonglong2 w = wv[q];
                    acc2[2*q]   = ffma2(w.x, g2, acc2[2*q]);
                    acc2[2*q+1] = ffma2(w.y, g2, acc2[2*q+1]);
                }
            }
        }
    }

    float inv_s = 1.f / (ascale[0] + 1e-8f);
    const float* conf = confidence + (size_t)b * HWc;

    #pragma unroll 1
    for (int s = 0; s < 2; s++) {
        int y = y0 + s;
        int rem = y * WW + x;

        float A[24];
        #pragma unroll
        for (int j = 0; j < 24; j++) {
            float2 f = unpk2(acc2[j]);
            A[j] = s ? f.y : f.x;
        }

        float av[8];
        #pragma unroll
        for (int j = 0; j < 8; j++) {
            float a  = tanhf(A[16 + j]) * inv_s;
            float ca = bilin_g(conf, (float)y + A[2*j], (float)x + A[2*j + 1]);
            av[j] = a * ca;
        }
        float ssum = 1e-4f;
        #pragma unroll
        for (int j = 0; j < 8; j++) ssum += fabsf(av[j]);
        ssum = fmaxf(ssum, 1.f);
        float asum = 0.f;
        #pragma unroll
        for (int j = 0; j < 8; j++) { av[j] = av[j] / ssum; asum += av[j]; }
        float aref = 1.f - asum;

        // exact fp32 outputs (streaming: never read again this launch)
        size_t ob = (size_t)b * 18 * HWc + rem;
        #pragma unroll
        for (int n = 0; n < 9; n++) {
            float oy, ox;
            if (n < 4)       { oy = A[2*n];         ox = A[2*n + 1]; }
            else if (n == 4) { oy = 0.f;            ox = 0.f; }
            else             { oy = A[2*(n-1)];     ox = A[2*(n-1) + 1]; }
            __stcs(&out_off[ob + (size_t)(2*n)     * HWc], oy);
            __stcs(&out_off[ob + (size_t)(2*n + 1) * HWc], ox);
        }
        size_t ab = (size_t)b * 9 * HWc + rem;
        #pragma unroll
        for (int n = 0; n < 9; n++) {
            float a = (n < 4) ? av[n] : (n == 4 ? aref : av[n - 1]);
            __stcs(&out_aff[ab + (size_t)n * HWc], a);
        }

        int pidx = b * HWc + rem;
        float fx = feat_fix[pidx];

        // 64B quantized record
        union { Rec r; int4 v[4]; } u;
        #pragma unroll
        for (int k = 0; k < 8; k++) {
            int qy = __float2int_rn(A[2*k]     * 4096.f);
            int qx = __float2int_rn(A[2*k + 1] * 4096.f);
            qy = max(-32767, min(32767, qy));
            qx = max(-32767, min(32767, qx));
            u.r.off[k] = make_short2((short)qy, (short)qx);
        }
        #pragma unroll
        for (int j = 0; j < 8; j++) {
            int q = __float2int_rn(av[j] * 16384.f);
            q = max(-32767, min(32767, q));
            u.r.affq[j] = (short)q;
        }
        u.r.acen = aref;
        u.r.fix  = fx;
        int4* rp = (int4*)&g_rec[pidx];
        rp[0] = u.v[0]; rp[1] = u.v[1]; rp[2] = u.v[2]; rp[3] = u.v[3];

        g_feat[0][pidx] = (fx > 0.f) ? fx : feat_init[pidx];
    }
}

// ---------------------------------------------------------------------------
// One propagation step, smem-tiled. Block = 16 rows x 64 cols useful (4 px
// per thread), tile = 27x75 (halo -5/+6; out-of-tile samples take the exact
// global fallback). No manual prefetch pipeline: records are loaded
// just-in-time and latency is hidden by occupancy (6 blocks/SM forced via
// launch bounds -> 48 resident warps).
// ---------------------------------------------------------------------------
#define TROWS 27
#define TCOLS 75

__global__ void __launch_bounds__(256, 6) prop_kernel(
    int ibuf, float* __restrict__ dout_feat, int last)
{
    __shared__ float tile[TROWS * TCOLS];

    int b   = blockIdx.z;
    int y0  = blockIdx.y * 16;
    int cx0 = blockIdx.x * 64;
    int ry0 = y0 - 5;
    int cxl = cx0 - 5;

    const float* __restrict__ fp = &g_feat[ibuf][b * HWc];

    #pragma unroll
    for (int i = threadIdx.x; i < TROWS * TCOLS; i += 256) {
        int r = i / TCOLS, c = i - r * TCOLS;
        int gy = ry0 + r, gxx = cxl + c;
        float v = 0.f;
        if (((unsigned)gy < (unsigned)HH) && ((unsigned)gxx < (unsigned)WW))
            v = fp[gy * WW + gxx];
        tile[i] = v;
    }
    __syncthreads();

    int lx  = threadIdx.x & 63;       // 0..63
    int lyg = threadIdx.x >> 6;       // 0..3
    int gx  = cx0 + lx;
    int pidx0 = b * HWc + (y0 + lyg * 4) * WW + gx;

    const float Qo = 1.f / 4096.f;
    const float Qa = 1.f / 16384.f;

    #pragma unroll
    for (int i = 0; i < 4; i++) {
        int rr   = lyg * 4 + i;       // useful-row index 0..15
        int pidx = pidx0 + i * WW;

        union { Rec r; unsigned long long v[8]; } u;
        {
            const char* rp = (const char*)&g_rec[pidx];
            ldg_el32(rp,      &u.v[0]);
            ldg_el32(rp + 32, &u.v[4]);
        }

        // center tap: exact fp32 affinity, offset exactly zero
        float sum = u.r.acen * tile[(rr + 5) * TCOLS + lx + 5];

        #pragma unroll
        for (int k = 0; k < 9; k++) {
            if (k == 4) continue;
            int j = (k < 4) ? k : k - 1;
            float a  = (float)u.r.affq[j] * Qa;
            float oy = (float)u.r.off[j].x * Qo;
            float ox = (float)u.r.off[j].y * Qo;
            float sy = (float)(rr + 5 + (k / 3) - 1) + oy;   // tile-local
            float sx = (float)(lx + 5 + (k % 3) - 1) + ox;
            float fy = floorf(sy), fxx = floorf(sx);
            int   iy = (int)fy,    ix  = (int)fxx;
            float wy = sy - fy,    wx  = sx - fxx;
            float v;
            if (((unsigned)iy < (unsigned)(TROWS - 1)) &&
                ((unsigned)ix < (unsigned)(TCOLS - 1))) {
                const float* tp = &tile[iy * TCOLS + ix];
                float v00 = tp[0],     v01 = tp[1];
                float v10 = tp[TCOLS], v11 = tp[TCOLS + 1];
                float v0 = fmaf(wx, v01 - v00, v00);
                float v1 = fmaf(wx, v11 - v10, v10);
                v = fmaf(wy, v1 - v0, v0);
            } else {
                v = bilin_g(fp, sy + (float)ry0, sx + (float)cxl);
            }
            sum = fmaf(a, v, sum);
        }

        if (last) {
            __stcs(&dout_feat[pidx], sum);
        } else {
            float fx = u.r.fix;
            g_feat[1 - ibuf][pidx] = (fx > 0.f) ? fx : sum;
        }
    }
}

extern "C" void kernel_launch(void* const* d_in, const int* in_sizes, int n_in,
                              void* d_out, int out_size) {
    const float* feat_init  = (const float*)d_in[0];
    const float* guidance   = (const float*)d_in[1];
    const float* confidence = (const float*)d_in[2];
    const float* feat_fix   = (const float*)d_in[3];
    const float* w_oa       = (const float*)d_in[4];
    const float* b_oa       = (const float*)d_in[5];
    const float* ascale     = (const float*)d_in[6];

    float* out      = (float*)d_out;
    float* out_feat = out;                         // B*1*H*W
    float* out_off  = out + (size_t)NPX;           // B*18*H*W
    float* out_aff  = out + (size_t)NPX * 19;      // B*9*H*W

    prep_kernel<<<(BB * 120 * WW + 255) / 256, 256>>>(
        guidance, confidence, feat_init, feat_fix, w_oa, b_oa, ascale,
        out_off, out_aff);

    dim3 pgrid(WW / 64, HH / 16, BB);              // 19 x 15 x 4 = 1140
    for (int it = 0; it < 18; ++it) {
        prop_kernel<<<pgrid, 256>>>(it & 1, out_feat, it == 17);
    }
}